// round 1
// baseline (speedup 1.0000x reference)
#include <cuda_runtime.h>

#define D      1024
#define NCOL   20000
#define TWO_M  512
#define DM1    1023
#define BLK    128
#define NBLK   ((NCOL + BLK - 1) / BLK)   // 157
#define FETA   1e-5f

// ---------------- scratch (device globals; no allocation allowed) ----------------
__device__ __align__(16) float g_S[BLK * BLK];   // block-local Gram  S[j][i] = x_j . x_i
__device__ float g_d[BLK];                        // d_i = g_w1 . x_i   (history dot)
__device__ float g_e[BLK];                        // e_i = v . a_i      (history dot for c-chain)
__device__ float g_sign[NCOL];
__device__ float g_c[NCOL];
__device__ float g_gw1[D];                        // sum_j sign_j x_j
__device__ float g_v[D];                          // sum_j c_j a_j  (index 1023 stays 0)
__device__ float g_x0[D];
__device__ float g_T0;
__device__ float g_q0;

// ---------------- init: zero state, gather x0, compute q0 ----------------
__global__ __launch_bounds__(1024) void init_kernel(const float* __restrict__ At,
                                                    const float* __restrict__ w1) {
    __shared__ float red[32];
    int tid = threadIdx.x;          // 1024 threads
    float x0 = At[(size_t)tid * NCOL];
    g_x0[tid] = x0;
    g_gw1[tid] = 0.0f;
    g_v[tid] = 0.0f;
    float p = w1[tid] * x0;
    #pragma unroll
    for (int o = 16; o; o >>= 1) p += __shfl_down_sync(0xffffffffu, p, o);
    if ((tid & 31) == 0) red[tid >> 5] = p;
    __syncthreads();
    if (tid < 32) {
        float q = red[tid];
        #pragma unroll
        for (int o = 16; o; o >>= 1) q += __shfl_down_sync(0xffffffffu, q, o);
        if (tid == 0) { g_q0 = q; g_T0 = 0.0f; }
    }
    for (int i = tid; i < BLK * BLK; i += 1024) g_S[i] = 0.0f;
    if (tid < BLK) { g_d[tid] = 0.0f; g_e[tid] = 0.0f; }
}

// ---------------- T0 = || W2_init @ a_0 ||^2 ----------------
__global__ __launch_bounds__(256) void t0_kernel(const float* __restrict__ W2) {
    __shared__ float red[8];
    int m = blockIdx.x;
    const float* row = W2 + (size_t)m * DM1;
    float p = 0.0f;
    for (int c = threadIdx.x; c < DM1; c += 256) p = fmaf(row[c], g_x0[c], p);
    #pragma unroll
    for (int o = 16; o; o >>= 1) p += __shfl_down_sync(0xffffffffu, p, o);
    if ((threadIdx.x & 31) == 0) red[threadIdx.x >> 5] = p;
    __syncthreads();
    if (threadIdx.x == 0) {
        float t = 0.0f;
        #pragma unroll
        for (int w = 0; w < 8; w++) t += red[w];
        atomicAdd(&g_T0, t * t);
    }
}

// ---------------- copy b into out[N..2N) ----------------
__global__ void copyb_kernel(const float* __restrict__ b, float* __restrict__ out) {
    int i = blockIdx.x * blockDim.x + threadIdx.x;
    if (i < NCOL) out[NCOL + i] = b[i];
}

// ---------------- per block: Gram S (upper triangle) + history GEMVs d,e ----------------
// grid = 16 K-slices of 64 rows, block = 256 threads (16x16, 8x8 register tile)
__global__ __launch_bounds__(256) void gram_kernel(const float* __restrict__ At, int s, int n) {
    __shared__ float sh[8][BLK];
    __shared__ float shw[64], shv[64];
    int tid = threadIdx.x;
    int r0 = blockIdx.x * 64;
    int ty = tid >> 4, tx = tid & 15;

    float acc[8][8];
    #pragma unroll
    for (int i = 0; i < 8; i++)
        #pragma unroll
        for (int j = 0; j < 8; j++) acc[i][j] = 0.0f;
    float du = 0.0f, eu = 0.0f;

    if (tid < 64) { shw[tid] = g_gw1[r0 + tid]; shv[tid] = g_v[r0 + tid]; }

    int linear = tid * 4;
    int rr = linear >> 7;          // staging row 0..7
    int cc = linear & 127;         // staging col (mult of 4)
    __syncthreads();

    for (int ch = 0; ch < 8; ch++) {
        int rbase = r0 + ch * 8;
        float4 val = make_float4(0.f, 0.f, 0.f, 0.f);
        if (cc < n) val = *(const float4*)(At + (size_t)(rbase + rr) * NCOL + s + cc);
        *(float4*)&sh[rr][cc] = val;
        __syncthreads();
        #pragma unroll
        for (int r2 = 0; r2 < 8; r2++) {
            float4 a4 = *(const float4*)&sh[r2][8 * ty];
            float4 a5 = *(const float4*)&sh[r2][8 * ty + 4];
            float4 b4 = *(const float4*)&sh[r2][8 * tx];
            float4 b5 = *(const float4*)&sh[r2][8 * tx + 4];
            float av[8] = {a4.x,a4.y,a4.z,a4.w,a5.x,a5.y,a5.z,a5.w};
            float bv[8] = {b4.x,b4.y,b4.z,b4.w,b5.x,b5.y,b5.z,b5.w};
            #pragma unroll
            for (int i = 0; i < 8; i++)
                #pragma unroll
                for (int j = 0; j < 8; j++) acc[i][j] = fmaf(av[i], bv[j], acc[i][j]);
        }
        if (tid < BLK) {
            #pragma unroll
            for (int r2 = 0; r2 < 8; r2++) {
                float xv = sh[r2][tid];
                du = fmaf(shw[ch * 8 + r2], xv, du);
                eu = fmaf(shv[ch * 8 + r2], xv, eu);   // g_v[1023]==0 -> a vs x handled
            }
        }
        __syncthreads();
    }
    #pragma unroll
    for (int i = 0; i < 8; i++) {
        int row = 8 * ty + i;
        if (row < n) {
            #pragma unroll
            for (int j = 0; j < 8; j++) {
                int col = 8 * tx + j;
                if (col > row && col < n) atomicAdd(&g_S[row * BLK + col], acc[i][j]);
            }
        }
    }
    if (tid < n) { atomicAdd(&g_d[tid], du); atomicAdd(&g_e[tid], eu); }
}

// ---------------- per block: serial scalar scan (c-chain + sign-chain fused) ----------------
// 1 CTA, warp 0 runs the chain; lane L owns columns 4L..4L+3 (rank-1 update scheme)
__global__ __launch_bounds__(256) void scan_kernel(const float* __restrict__ At,
                                                   const float* __restrict__ b,
                                                   float* __restrict__ out, int s, int n) {
    extern __shared__ float smS[];                       // BLK*BLK Gram copy
    __shared__ float sh_pd[BLK], sh_pe[BLK], sh_nb2[BLK], sh_z[BLK];
    __shared__ float sh_sc[BLK], sh_sg[BLK], sh_c[BLK];
    int tid = threadIdx.x;

    for (int j = tid; j < (BLK * BLK) / 4; j += blockDim.x)
        ((float4*)smS)[j] = ((const float4*)g_S)[j];
    if (tid < BLK) {
        if (tid < n) {
            sh_pd[tid]  = -FETA * g_d[tid];
            sh_pe[tid]  = -2.0f * FETA * g_e[tid];
            sh_nb2[tid] = -2.0f * b[s + tid];
            sh_z[tid]   = At[(size_t)DM1 * NCOL + s + tid];
        } else {
            sh_pd[tid] = 0.f; sh_pe[tid] = 0.f; sh_nb2[tid] = 0.f; sh_z[tid] = 0.f;
        }
    }
    __syncthreads();

    if (tid < 32) {
        const int lane = tid;
        const int base = 4 * lane;
        const float T0 = g_T0;
        const float q0T0 = g_q0 + T0;
        const float z0 = sh_z[base], z1 = sh_z[base + 1], z2 = sh_z[base + 2], z3 = sh_z[base + 3];
        float aC0 = 0.f, aC1 = 0.f, aC2 = 0.f, aC3 = 0.f;   // sum c_j * G[j][col]
        float aS0 = 0.f, aS1 = 0.f, aS2 = 0.f, aS3 = 0.f;   // sum sign_j * S[j][col]
        const int ngroups = n >> 2;

        for (int g = 0; g < ngroups; g++) {
            #pragma unroll
            for (int sub = 0; sub < 4; sub++) {
                const int i = 4 * g + sub;
                // every lane computes with its own acc; shfl selects the owner (lane g)
                float ac = (sub == 0) ? aC0 : (sub == 1) ? aC1 : (sub == 2) ? aC2 : aC3;
                float as = (sub == 0) ? aS0 : (sub == 1) ? aS1 : (sub == 2) ? aS2 : aS3;
                float ci = fmaf(ac, -2.0f * FETA, sh_pe[i]);
                float scal = fmaf(as, -FETA, sh_pd[i]);
                scal = fmaf(ci * ci, T0, scal);
                if (s + i == 0) { ci = 1.0f; scal = q0T0; }   // step 0 uses w1_init / W2_init
                float sg = fmaf(scal, 2.0f, sh_nb2[i]);
                if (lane == g) { sh_sc[i] = scal; sh_sg[i] = sg; sh_c[i] = ci; }
                ci = __shfl_sync(0xffffffffu, ci, g);
                sg = __shfl_sync(0xffffffffu, sg, g);
                float4 v = *(const float4*)&smS[i * BLK + base];
                float zi = sh_z[i];
                if (base + 0 > i) { aS0 = fmaf(sg, v.x, aS0); aC0 = fmaf(ci, fmaf(-zi, z0, v.x), aC0); }
                if (base + 1 > i) { aS1 = fmaf(sg, v.y, aS1); aC1 = fmaf(ci, fmaf(-zi, z1, v.y), aC1); }
                if (base + 2 > i) { aS2 = fmaf(sg, v.z, aS2); aC2 = fmaf(ci, fmaf(-zi, z2, v.z), aC2); }
                if (base + 3 > i) { aS3 = fmaf(sg, v.w, aS3); aC3 = fmaf(ci, fmaf(-zi, z3, v.w), aC3); }
            }
        }
    }
    __syncthreads();
    if (tid < n) {
        out[s + tid]    = sh_sc[tid];
        g_sign[s + tid] = sh_sg[tid];
        g_c[s + tid]    = sh_c[tid];
    }
    // zero scratch for the NEXT block's gram atomics
    for (int j = tid; j < BLK * BLK; j += blockDim.x) g_S[j] = 0.0f;
    if (tid < BLK) { g_d[tid] = 0.0f; g_e[tid] = 0.0f; }
}

// ---------------- per block: g_w1 += X_blk @ sign,  v += A_blk @ c ----------------
__global__ __launch_bounds__(256) void update_kernel(const float* __restrict__ At, int s, int n) {
    __shared__ float ssg[BLK], scc[BLK];
    int tid = threadIdx.x;
    int r = blockIdx.x * 256 + tid;          // grid=4 -> r in [0,1024)
    if (tid < n) { ssg[tid] = g_sign[s + tid]; scc[tid] = g_c[s + tid]; }
    __syncthreads();
    const float4* row4 = (const float4*)(At + (size_t)r * NCOL + s);
    float w = g_gw1[r], v = g_v[r];
    int n4 = n >> 2;
    for (int i4 = 0; i4 < n4; i4++) {
        float4 xv = row4[i4];
        int ib = i4 * 4;
        w = fmaf(ssg[ib + 0], xv.x, w); v = fmaf(scc[ib + 0], xv.x, v);
        w = fmaf(ssg[ib + 1], xv.y, w); v = fmaf(scc[ib + 1], xv.y, v);
        w = fmaf(ssg[ib + 2], xv.z, w); v = fmaf(scc[ib + 2], xv.z, v);
        w = fmaf(ssg[ib + 3], xv.w, w); v = fmaf(scc[ib + 3], xv.w, v);
    }
    g_gw1[r] = w;
    if (r < DM1) g_v[r] = v;                 // keep g_v[1023] == 0 forever (a = x[:-1])
}

// ---------------- launch ----------------
extern "C" void kernel_launch(void* const* d_in, const int* in_sizes, int n_in,
                              void* d_out, int out_size) {
    const float* At = (const float*)d_in[0];
    const float* b  = (const float*)d_in[1];
    const float* w1 = (const float*)d_in[2];
    const float* W2 = (const float*)d_in[3];
    float* out = (float*)d_out;

    cudaFuncSetAttribute(scan_kernel, cudaFuncAttributeMaxDynamicSharedMemorySize,
                         BLK * BLK * (int)sizeof(float));

    init_kernel<<<1, 1024>>>(At, w1);
    t0_kernel<<<TWO_M, 256>>>(W2);
    if (out_size >= 2 * NCOL)
        copyb_kernel<<<(NCOL + 255) / 256, 256>>>(b, out);

    for (int k = 0; k < NBLK; k++) {
        int s = k * BLK;
        int n = NCOL - s; if (n > BLK) n = BLK;
        gram_kernel<<<16, 256>>>(At, s, n);
        scan_kernel<<<1, 256, BLK * BLK * sizeof(float)>>>(At, b, out, s, n);
        update_kernel<<<4, 256>>>(At, s, n);
    }
}

// round 2
// speedup vs baseline: 2.0182x; 2.0182x over previous
#include <cuda_runtime.h>

#define D      1024
#define NCOL   20000
#define TWO_M  512
#define DM1    1023
#define BLK    128
#define NBLK   ((NCOL + BLK - 1) / BLK)   // 157
#define FETA   1e-5f

// ---------------- scratch (device globals; no allocation allowed) ----------------
__device__ __align__(16) float g_Sall[NBLK * BLK * BLK];  // all diag Gram blocks (10.3 MB)
__device__ float g_d[BLK];                 // d_i = g_w1 . x_i   (history dot, current block)
__device__ float g_e[BLK];                 // e_i = v . a_i
__device__ float g_sign[NCOL];
__device__ float g_c[NCOL];
__device__ float g_gw1[D];                 // sum_j sign_j x_j
__device__ float g_v[D];                   // sum_j c_j a_j  (index 1023 stays 0)
__device__ float g_x0[D];
__device__ float g_T0;
__device__ float g_q0;

// ---------------- zero the Gram slab (gram_all accumulates with atomics) ----------------
__global__ void zero_sall_kernel() {
    int i = blockIdx.x * blockDim.x + threadIdx.x;   // 2512*256 = 643072 float4 exactly
    ((float4*)g_Sall)[i] = make_float4(0.f, 0.f, 0.f, 0.f);
}

// ---------------- init: zero state, gather x0, compute q0 ----------------
__global__ __launch_bounds__(1024) void init_kernel(const float* __restrict__ At,
                                                    const float* __restrict__ w1) {
    __shared__ float red[32];
    int tid = threadIdx.x;          // 1024 threads
    float x0 = At[(size_t)tid * NCOL];
    g_x0[tid] = x0;
    g_gw1[tid] = 0.0f;
    g_v[tid] = 0.0f;
    float p = w1[tid] * x0;
    #pragma unroll
    for (int o = 16; o; o >>= 1) p += __shfl_down_sync(0xffffffffu, p, o);
    if ((tid & 31) == 0) red[tid >> 5] = p;
    __syncthreads();
    if (tid < 32) {
        float q = red[tid];
        #pragma unroll
        for (int o = 16; o; o >>= 1) q += __shfl_down_sync(0xffffffffu, q, o);
        if (tid == 0) { g_q0 = q; g_T0 = 0.0f; }
    }
    if (tid < BLK) { g_d[tid] = 0.0f; g_e[tid] = 0.0f; }
}

// ---------------- T0 = || W2_init @ a_0 ||^2 ----------------
__global__ __launch_bounds__(256) void t0_kernel(const float* __restrict__ W2) {
    __shared__ float red[8];
    int m = blockIdx.x;
    const float* row = W2 + (size_t)m * DM1;
    float p = 0.0f;
    for (int c = threadIdx.x; c < DM1; c += 256) p = fmaf(row[c], g_x0[c], p);
    #pragma unroll
    for (int o = 16; o; o >>= 1) p += __shfl_down_sync(0xffffffffu, p, o);
    if ((threadIdx.x & 31) == 0) red[threadIdx.x >> 5] = p;
    __syncthreads();
    if (threadIdx.x == 0) {
        float t = 0.0f;
        #pragma unroll
        for (int w = 0; w < 8; w++) t += red[w];
        atomicAdd(&g_T0, t * t);
    }
}

// ---------------- copy b into out[N..2N) ----------------
__global__ void copyb_kernel(const float* __restrict__ b, float* __restrict__ out) {
    int i = blockIdx.x * blockDim.x + threadIdx.x;
    if (i < NCOL) out[NCOL + i] = b[i];
}

// ---------------- ALL diag Gram blocks, fully parallel ----------------
// grid = (NBLK, 2): one block index x K-half; block = 256 (16x16 threads, 8x8 reg tile)
__global__ __launch_bounds__(256) void gram_all_kernel(const float* __restrict__ At) {
    __shared__ float sh[32][BLK];
    int k = blockIdx.x;
    int s = k * BLK;
    int kh = blockIdx.y;                 // K-half: rows [kh*512, kh*512+512)
    int tid = threadIdx.x;
    int ty = tid >> 4, tx = tid & 15;

    float acc[8][8];
    #pragma unroll
    for (int i = 0; i < 8; i++)
        #pragma unroll
        for (int j = 0; j < 8; j++) acc[i][j] = 0.0f;

    for (int kt = 0; kt < 16; kt++) {
        int r0 = kh * 512 + kt * 32;
        #pragma unroll
        for (int i = 0; i < 4; i++) {
            int f = tid + 256 * i;               // 1024 float4 total
            int r = f >> 5;
            int c4 = (f & 31) * 4;
            float4 v = make_float4(0.f, 0.f, 0.f, 0.f);
            if (s + c4 + 4 <= NCOL)
                v = *(const float4*)(At + (size_t)(r0 + r) * NCOL + s + c4);
            *(float4*)&sh[r][c4] = v;
        }
        __syncthreads();
        #pragma unroll 4
        for (int r2 = 0; r2 < 32; r2++) {
            float4 a4 = *(const float4*)&sh[r2][8 * ty];
            float4 a5 = *(const float4*)&sh[r2][8 * ty + 4];
            float4 b4 = *(const float4*)&sh[r2][8 * tx];
            float4 b5 = *(const float4*)&sh[r2][8 * tx + 4];
            float av[8] = {a4.x,a4.y,a4.z,a4.w,a5.x,a5.y,a5.z,a5.w};
            float bv[8] = {b4.x,b4.y,b4.z,b4.w,b5.x,b5.y,b5.z,b5.w};
            #pragma unroll
            for (int i = 0; i < 8; i++)
                #pragma unroll
                for (int j = 0; j < 8; j++) acc[i][j] = fmaf(av[i], bv[j], acc[i][j]);
        }
        __syncthreads();
    }
    float* Sk = g_Sall + (size_t)k * BLK * BLK;
    #pragma unroll
    for (int i = 0; i < 8; i++) {
        int row = 8 * ty + i;
        #pragma unroll
        for (int j = 0; j < 8; j++) {
            int col = 8 * tx + j;
            if (col > row) atomicAdd(&Sk[row * BLK + col], acc[i][j]);
        }
    }
}

// ---------------- per block: serial scalar scan (c-chain + sign-chain fused) ----------------
// 1 CTA, warp 0 runs the chain; lane L owns columns 4L..4L+3 (rank-1 update scheme)
__global__ __launch_bounds__(256) void scan_kernel(const float* __restrict__ At,
                                                   const float* __restrict__ b,
                                                   float* __restrict__ out,
                                                   int k, int s, int n) {
    extern __shared__ float smS[];                       // BLK*BLK Gram copy
    __shared__ float sh_pd[BLK], sh_pe[BLK], sh_nb2[BLK], sh_z[BLK];
    __shared__ float sh_sc[BLK], sh_sg[BLK], sh_c[BLK];
    int tid = threadIdx.x;

    const float4* Sk4 = (const float4*)(g_Sall + (size_t)k * BLK * BLK);
    #pragma unroll 4
    for (int j = tid; j < (BLK * BLK) / 4; j += 256)
        ((float4*)smS)[j] = Sk4[j];
    if (tid < BLK) {
        if (tid < n) {
            sh_pd[tid]  = -FETA * g_d[tid];
            sh_pe[tid]  = -2.0f * FETA * g_e[tid];
            sh_nb2[tid] = -2.0f * b[s + tid];
            sh_z[tid]   = At[(size_t)DM1 * NCOL + s + tid];
        } else {
            sh_pd[tid] = 0.f; sh_pe[tid] = 0.f; sh_nb2[tid] = 0.f; sh_z[tid] = 0.f;
        }
    }
    __syncthreads();

    if (tid < 32) {
        const int lane = tid;
        const int base = 4 * lane;
        const float T0 = g_T0;
        const float q0T0 = g_q0 + T0;
        const float z0 = sh_z[base], z1 = sh_z[base + 1], z2 = sh_z[base + 2], z3 = sh_z[base + 3];
        float aC0 = 0.f, aC1 = 0.f, aC2 = 0.f, aC3 = 0.f;   // sum c_j * G[j][col]
        float aS0 = 0.f, aS1 = 0.f, aS2 = 0.f, aS3 = 0.f;   // sum sign_j * S[j][col]
        const int ngroups = n >> 2;

        for (int g = 0; g < ngroups; g++) {
            #pragma unroll
            for (int sub = 0; sub < 4; sub++) {
                const int i = 4 * g + sub;
                float ac = (sub == 0) ? aC0 : (sub == 1) ? aC1 : (sub == 2) ? aC2 : aC3;
                float as = (sub == 0) ? aS0 : (sub == 1) ? aS1 : (sub == 2) ? aS2 : aS3;
                float ci = fmaf(ac, -2.0f * FETA, sh_pe[i]);
                float scal = fmaf(as, -FETA, sh_pd[i]);
                scal = fmaf(ci * ci, T0, scal);
                if (s + i == 0) { ci = 1.0f; scal = q0T0; }   // step 0 uses w1_init / W2_init
                float sg = fmaf(scal, 2.0f, sh_nb2[i]);
                if (lane == g) { sh_sc[i] = scal; sh_sg[i] = sg; sh_c[i] = ci; }
                ci = __shfl_sync(0xffffffffu, ci, g);
                sg = __shfl_sync(0xffffffffu, sg, g);
                float4 v = *(const float4*)&smS[i * BLK + base];
                float zi = sh_z[i];
                if (base + 0 > i) { aS0 = fmaf(sg, v.x, aS0); aC0 = fmaf(ci, fmaf(-zi, z0, v.x), aC0); }
                if (base + 1 > i) { aS1 = fmaf(sg, v.y, aS1); aC1 = fmaf(ci, fmaf(-zi, z1, v.y), aC1); }
                if (base + 2 > i) { aS2 = fmaf(sg, v.z, aS2); aC2 = fmaf(ci, fmaf(-zi, z2, v.z), aC2); }
                if (base + 3 > i) { aS3 = fmaf(sg, v.w, aS3); aC3 = fmaf(ci, fmaf(-zi, z3, v.w), aC3); }
            }
        }
    }
    __syncthreads();
    if (tid < n) {
        out[s + tid]    = sh_sc[tid];
        g_sign[s + tid] = sh_sg[tid];
        g_c[s + tid]    = sh_c[tid];
    }
    // zero history-dot accumulators for the NEXT block's upde atomics
    if (tid >= BLK && tid < 2 * BLK) { g_d[tid - BLK] = 0.0f; g_e[tid - BLK] = 0.0f; }
}

// ---------------- fused: gw1,v += block k;  then d,e for block k+1 ----------------
// grid = 16 CTAs, each owns 64 rows. Phase A: rank-128 row update (regs).
// Phase B: next block's history GEMV using just-updated row values from smem.
__global__ __launch_bounds__(256) void upde_kernel(const float* __restrict__ At, int s) {
    __shared__ float ssg[BLK], scc[BLK];
    __shared__ float sgw[64], sv[64];
    __shared__ float xs[64][BLK];
    int tid = threadIdx.x;
    int r0 = blockIdx.x * 64;

    if (tid < BLK) { ssg[tid] = g_sign[s + tid]; scc[tid] = g_c[s + tid]; }
    __syncthreads();

    // Phase A: thread group of 4 per row; q-th quarter handles 32 cols
    int row = r0 + (tid >> 2);
    int q   = tid & 3;
    const float4* rp = (const float4*)(At + (size_t)row * NCOL + s);
    float w = 0.0f, v = 0.0f;
    #pragma unroll
    for (int i = 0; i < 8; i++) {
        float4 xv = rp[q * 8 + i];
        int ib = q * 32 + i * 4;
        w = fmaf(ssg[ib + 0], xv.x, w); v = fmaf(scc[ib + 0], xv.x, v);
        w = fmaf(ssg[ib + 1], xv.y, w); v = fmaf(scc[ib + 1], xv.y, v);
        w = fmaf(ssg[ib + 2], xv.z, w); v = fmaf(scc[ib + 2], xv.z, v);
        w = fmaf(ssg[ib + 3], xv.w, w); v = fmaf(scc[ib + 3], xv.w, v);
    }
    w += __shfl_xor_sync(0xffffffffu, w, 1); w += __shfl_xor_sync(0xffffffffu, w, 2);
    v += __shfl_xor_sync(0xffffffffu, v, 1); v += __shfl_xor_sync(0xffffffffu, v, 2);
    if (q == 0) {
        float gw = g_gw1[row] + w;
        g_gw1[row] = gw;
        sgw[tid >> 2] = gw;
        if (row < DM1) {
            float gv = g_v[row] + v;
            g_v[row] = gv;
            sv[tid >> 2] = gv;
        } else {
            sv[tid >> 2] = 0.0f;        // a excludes feature 1023
        }
    }
    __syncthreads();

    // Phase B: stage At block k+1 (64 rows x 128 cols) and do history dots
    int s1 = s + BLK;
    #pragma unroll
    for (int i = 0; i < 8; i++) {
        int f = tid + 256 * i;                  // 2048 float4
        int r = f >> 5;
        int c4 = (f & 31) * 4;
        float4 vv = make_float4(0.f, 0.f, 0.f, 0.f);
        if (s1 + c4 + 4 <= NCOL)
            vv = *(const float4*)(At + (size_t)(r0 + r) * NCOL + s1 + c4);
        *(float4*)&xs[r][c4] = vv;
    }
    __syncthreads();

    int c = tid & 127;
    const float* wv = (tid >= 128) ? sv : sgw;
    float acc = 0.0f;
    #pragma unroll 8
    for (int r = 0; r < 64; r++) acc = fmaf(wv[r], xs[r][c], acc);
    if (tid >= 128) atomicAdd(&g_e[c], acc);
    else            atomicAdd(&g_d[c], acc);
}

// ---------------- launch ----------------
extern "C" void kernel_launch(void* const* d_in, const int* in_sizes, int n_in,
                              void* d_out, int out_size) {
    const float* At = (const float*)d_in[0];
    const float* b  = (const float*)d_in[1];
    const float* w1 = (const float*)d_in[2];
    const float* W2 = (const float*)d_in[3];
    float* out = (float*)d_out;

    cudaFuncSetAttribute(scan_kernel, cudaFuncAttributeMaxDynamicSharedMemorySize,
                         BLK * BLK * (int)sizeof(float));

    zero_sall_kernel<<<2512, 256>>>();
    init_kernel<<<1, 1024>>>(At, w1);
    t0_kernel<<<TWO_M, 256>>>(W2);
    if (out_size >= 2 * NCOL)
        copyb_kernel<<<(NCOL + 255) / 256, 256>>>(b, out);
    gram_all_kernel<<<dim3(NBLK, 2), 256>>>(At);

    for (int k = 0; k < NBLK; k++) {
        int s = k * BLK;
        int n = NCOL - s; if (n > BLK) n = BLK;
        scan_kernel<<<1, 256, BLK * BLK * sizeof(float)>>>(At, b, out, k, s, n);
        if (k + 1 < NBLK)
            upde_kernel<<<16, 256>>>(At, s);
    }
}